// round 3
// baseline (speedup 1.0000x reference)
#include <cuda_runtime.h>
#include <math.h>

// Problem constants (fixed shapes from reference)
#define N_ROWS 32768          // 8 * 4096
#define IN_F   256
#define OUT_F  256
#define K_SPL  2048           // IN_F * 8 coefs
#define K_TOT  2304           // IN_F + K_SPL

// Fused GEMM tiling
#define BM 128
#define BN 128
#define BC 16                 // K-chunk staged in smem (divides 256 boundary)
#define NCH (K_TOT / BC)      // 144 chunks; first 16 silu, last 128 spline

typedef unsigned long long ull;

// ---------------------------------------------------------------------------
// Packed fp32x2 helpers (FFMA2 — only reachable via PTX on sm_103a)
// ---------------------------------------------------------------------------
__device__ __forceinline__ void fma2(ull& d, ull a, ull b) {
    asm("fma.rn.f32x2 %0, %1, %2, %0;" : "+l"(d) : "l"(a), "l"(b));
}
__device__ __forceinline__ float2 ull_as_f2(ull v) {
    float2 f;
    asm("mov.b64 {%0, %1}, %2;" : "=f"(f.x), "=f"(f.y) : "l"(v));
    return f;
}

__device__ __forceinline__ float silu_f(float xv) {
    // x * sigmoid(x). Fast exp/div: ~1e-6 rel error, far inside 1e-3 budget.
    return __fdividef(xv, 1.0f + __expf(-xv));
}

// Uniform cubic B-spline closed form.
// grid[m] = m*0.4 - 2.2, m=0..11 -> u = (x+2.2)*2.5, interval j = floor(u),
// f = u - j. Nonzero cubic bases c = j-3..j (clipped to [0,7]) with weights
// {(1-f)^3, 3f^3-6f^2+4, -3f^3+3f^2+3f+1, f^3}/6. Outside [-2.2,2.2): all 0.
__device__ __forceinline__ void bspline8(float xv, float bb[8]) {
    #pragma unroll
    for (int c = 0; c < 8; ++c) bb[c] = 0.0f;
    float u = (xv + 2.2f) * 2.5f;
    if (u >= 0.0f && u < 11.0f) {
        float fj = floorf(u);
        int   j  = (int)fj;
        float f  = u - fj;
        float mf = 1.0f - f;
        float f2 = f * f;
        float f3 = f2 * f;
        const float c6 = 1.0f / 6.0f;
        float w0 = mf * mf * mf * c6;                                // c = j-3
        float w1 = (3.0f * f3 - 6.0f * f2 + 4.0f) * c6;              // c = j-2
        float w2 = (-3.0f * f3 + 3.0f * f2 + 3.0f * f + 1.0f) * c6;  // c = j-1
        float w3 = f3 * c6;                                          // c = j
        #pragma unroll
        for (int c = 0; c < 8; ++c) {
            float v = 0.0f;
            v = (j - 3 == c) ? w0 : v;
            v = (j - 2 == c) ? w1 : v;
            v = (j - 1 == c) ? w2 : v;
            v = (j     == c) ? w3 : v;
            bb[c] = v;
        }
    }
}

// ---------------------------------------------------------------------------
// Fused kernel: C[N_ROWS, OUT_F] = F @ W^T with F generated on the fly.
// F[n, k]  = silu(x[n,k])                      for k <  256
//          = B_{(k-256)&7}( x[n, (k-256)>>3] ) for k >= 256
// W[o, k]  = base_weight[o,k] (k<256) else spline_weight flat [OUT, IN*8].
// 128x128 CTA tile, 256 threads, 8x8 C-subtile/thread, fp32x2 packed FMA.
// A staged PRE-DUPLICATED (As2[k][2r]=As2[k][2r+1]) so the packed FFMA2
// operand comes from LDS.128 with zero MOV-duplication instructions.
// ---------------------------------------------------------------------------
__global__ __launch_bounds__(256, 2) void kan_fused_kernel(
    const float* __restrict__ x,
    const float* __restrict__ Wb,
    const float* __restrict__ Ws,
    float* __restrict__ out)
{
    __shared__ float As2[BC][2 * BM];   // 16 KB, A duplicated pairwise
    __shared__ float Bs [BC][BN];       //  8 KB

    const int tid = threadIdx.x;
    const int n0  = blockIdx.y * BM;
    const int o0  = blockIdx.x * BN;
    const int tm0 = (tid >> 4) * 8;   // C-tile row base
    const int tn0 = (tid & 15) * 8;   // C-tile col base

    ull acc[8][4];
    #pragma unroll
    for (int m = 0; m < 8; ++m)
        #pragma unroll
        for (int j = 0; j < 4; ++j)
            acc[m][j] = 0ull;

    float4 bPre[2];     // next W chunk: one o-row, 4 consecutive k per slot
    float4 aPre[2];     // next x (silu chunk): one row, 4 consecutive k
    float  xSpl;        // next x (spline chunk): one scalar per thread

    // ---- register prefetch of chunk ck's global data ----
    auto fill = [&](int ck) {
        const int k0 = ck * BC;
        #pragma unroll
        for (int p = 0; p < 2; ++p) {
            int s  = tid + p * 256;       // [0, 512)
            int o  = s & 127;
            int kq = (s >> 7) * 4;        // {0,4,8,12}
            int gk = k0 + kq;
            const float* src = (gk < IN_F)
                ? (Wb + (size_t)(o0 + o) * IN_F + gk)
                : (Ws + (size_t)(o0 + o) * K_SPL + (gk - IN_F));
            bPre[p] = *reinterpret_cast<const float4*>(src);
        }
        if (k0 < IN_F) {
            #pragma unroll
            for (int p = 0; p < 2; ++p) {
                int s   = tid + p * 256;
                int row = s & 127;
                int kq  = (s >> 7) * 4;
                aPre[p] = *reinterpret_cast<const float4*>(
                    &x[(size_t)(n0 + row) * IN_F + k0 + kq]);
            }
        } else {
            // 2 features per chunk: 256 scalars, 1 per thread.
            int i0  = (k0 - IN_F) >> 3;
            int row = tid & 127;
            int li  = tid >> 7;           // 0 or 1
            xSpl = x[(size_t)(n0 + row) * IN_F + i0 + li];
        }
    };

    // ---- store prefetched data into smem (computing features) ----
    auto store = [&](int ck) {
        const int k0 = ck * BC;
        #pragma unroll
        for (int p = 0; p < 2; ++p) {
            int s  = tid + p * 256;
            int o  = s & 127;
            int kq = (s >> 7) * 4;
            Bs[kq + 0][o] = bPre[p].x;
            Bs[kq + 1][o] = bPre[p].y;
            Bs[kq + 2][o] = bPre[p].z;
            Bs[kq + 3][o] = bPre[p].w;
        }
        if (k0 < IN_F) {
            #pragma unroll
            for (int p = 0; p < 2; ++p) {
                int s   = tid + p * 256;
                int row = s & 127;
                int kq  = (s >> 7) * 4;
                float v0 = silu_f(aPre[p].x);
                float v1 = silu_f(aPre[p].y);
                float v2 = silu_f(aPre[p].z);
                float v3 = silu_f(aPre[p].w);
                *reinterpret_cast<float2*>(&As2[kq + 0][2 * row]) = make_float2(v0, v0);
                *reinterpret_cast<float2*>(&As2[kq + 1][2 * row]) = make_float2(v1, v1);
                *reinterpret_cast<float2*>(&As2[kq + 2][2 * row]) = make_float2(v2, v2);
                *reinterpret_cast<float2*>(&As2[kq + 3][2 * row]) = make_float2(v3, v3);
            }
        } else {
            int row = tid & 127;
            int li  = tid >> 7;
            float bb[8];
            bspline8(xSpl, bb);
            #pragma unroll
            for (int c = 0; c < 8; ++c)
                *reinterpret_cast<float2*>(&As2[li * 8 + c][2 * row]) =
                    make_float2(bb[c], bb[c]);
        }
    };

    fill(0);
    for (int ck = 0; ck < NCH; ++ck) {
        __syncthreads();     // previous compute done before overwriting smem
        store(ck);
        __syncthreads();
        if (ck + 1 < NCH)
            fill(ck + 1);    // LDG latency hides under the FMA phase

        #pragma unroll
        for (int k = 0; k < BC; ++k) {
            // A: 8 pre-duplicated pairs = 64B contiguous = 4x LDS.128
            //    (2 distinct addresses per warp -> broadcast, conflict-free)
            const ull* ap = reinterpret_cast<const ull*>(&As2[k][2 * tm0]);
            // B: 8 consecutive cols = 32B = 2x LDS.128 (contiguous per warp)
            const ull* bp = reinterpret_cast<const ull*>(&Bs[k][tn0]);
            ull ad[8], bv[4];
            #pragma unroll
            for (int m = 0; m < 8; ++m) ad[m] = ap[m];
            #pragma unroll
            for (int j = 0; j < 4; ++j) bv[j] = bp[j];
            #pragma unroll
            for (int m = 0; m < 8; ++m)
                #pragma unroll
                for (int j = 0; j < 4; ++j)
                    fma2(acc[m][j], ad[m], bv[j]);
        }
    }

    // Epilogue: each thread writes its 8x8 block as 2 float4 per row.
    #pragma unroll
    for (int m = 0; m < 8; ++m) {
        float2 p0 = ull_as_f2(acc[m][0]);
        float2 p1 = ull_as_f2(acc[m][1]);
        float2 p2 = ull_as_f2(acc[m][2]);
        float2 p3 = ull_as_f2(acc[m][3]);
        float4* op = reinterpret_cast<float4*>(
            out + (size_t)(n0 + tm0 + m) * OUT_F + o0 + tn0);
        op[0] = make_float4(p0.x, p0.y, p1.x, p1.y);
        op[1] = make_float4(p2.x, p2.y, p3.x, p3.y);
    }
}

// ---------------------------------------------------------------------------
extern "C" void kernel_launch(void* const* d_in, const int* in_sizes, int n_in,
                              void* d_out, int out_size) {
    const float* x  = (const float*)d_in[0];   // [8, 4096, 256]
    const float* wb = (const float*)d_in[1];   // [256, 256]
    const float* ws = (const float*)d_in[2];   // [256, 256, 8]
    float* out = (float*)d_out;                // [8, 4096, 256]

    dim3 grid(OUT_F / BN, N_ROWS / BM);        // (2, 256)
    kan_fused_kernel<<<grid, 256>>>(x, wb, ws, out);
}

// round 10
// speedup vs baseline: 2.8866x; 2.8866x over previous
#include <cuda_runtime.h>
#include <cuda_bf16.h>
#include <stdint.h>
#include <math.h>

// ---------------- problem constants ----------------
#define N_ROWS 32768          // 8 * 4096
#define IN_F   256
#define OUT_F  256
#define K_SPL  2048
#define K_TOT  2304

// ---------------- tiling ----------------
#define BM 128                // rows per CTA
#define BN 128                // out cols per CTA
#define KC 64                 // K-cols per staged chunk
#define NCH (K_TOT / KC)      // 36 chunks; 0..3 silu, 4..35 spline
#define PAD 8
#define LDA (KC + PAD)        // 72 bf16 per smem row (144 B: ldmatrix conflict-free)

#define TILE_E  (BM * LDA)    // 9216 bf16 per tile
#define STAGE_E (4 * TILE_E)  // Ah | Al | Bh | Bl
#define SM_BYTES (2 * STAGE_E * 2)   // double buffer, 147456 B

// Pre-split weights W[o,k] (k<256: base, else spline flat) as bf16 hi/lo.
__device__ __nv_bfloat16 g_w_hi[(size_t)OUT_F * K_TOT];
__device__ __nv_bfloat16 g_w_lo[(size_t)OUT_F * K_TOT];

// ---------------- PTX helpers (baseline ISA only: sm_80-era, compute_103-safe) --
__device__ __forceinline__ uint32_t smem_u32(const void* p) {
    uint32_t a;
    asm("{ .reg .u64 t; cvta.to.shared.u64 t, %1; cvt.u32.u64 %0, t; }"
        : "=r"(a) : "l"(p));
    return a;
}
__device__ __forceinline__ void ldsm_x4(uint32_t r[4], uint32_t addr) {
    asm volatile("ldmatrix.sync.aligned.m8n8.x4.shared.b16 {%0,%1,%2,%3}, [%4];"
                 : "=r"(r[0]), "=r"(r[1]), "=r"(r[2]), "=r"(r[3]) : "r"(addr));
}
__device__ __forceinline__ void mma_bf16(float c[4], const uint32_t a[4],
                                         uint32_t b0, uint32_t b1) {
    asm volatile(
        "mma.sync.aligned.m16n8k16.row.col.f32.bf16.bf16.f32 "
        "{%0,%1,%2,%3}, {%4,%5,%6,%7}, {%8,%9}, {%0,%1,%2,%3};"
        : "+f"(c[0]), "+f"(c[1]), "+f"(c[2]), "+f"(c[3])
        : "r"(a[0]), "r"(a[1]), "r"(a[2]), "r"(a[3]), "r"(b0), "r"(b1));
}

// ---------------- math helpers ----------------
__device__ __forceinline__ float silu_f(float xv) {
    return __fdividef(xv, 1.0f + __expf(-xv));
}
// Uniform cubic B-spline closed form (verified rel_err 7e-7 vs reference):
// u = (x+2.2)*2.5, j = floor(u), nonzero bases c = j-3..j clipped to [0,7].
__device__ __forceinline__ void bspline8(float xv, float bb[8]) {
    #pragma unroll
    for (int c = 0; c < 8; ++c) bb[c] = 0.0f;
    float u = (xv + 2.2f) * 2.5f;
    if (u >= 0.0f && u < 11.0f) {
        float fj = floorf(u);
        int   j  = (int)fj;
        float f  = u - fj;
        float mf = 1.0f - f;
        float f2 = f * f, f3 = f2 * f;
        const float c6 = 1.0f / 6.0f;
        float w0 = mf * mf * mf * c6;
        float w1 = (3.0f * f3 - 6.0f * f2 + 4.0f) * c6;
        float w2 = (-3.0f * f3 + 3.0f * f2 + 3.0f * f + 1.0f) * c6;
        float w3 = f3 * c6;
        #pragma unroll
        for (int c = 0; c < 8; ++c) {
            float v = 0.0f;
            v = (j - 3 == c) ? w0 : v;
            v = (j - 2 == c) ? w1 : v;
            v = (j - 1 == c) ? w2 : v;
            v = (j     == c) ? w3 : v;
            bb[c] = v;
        }
    }
}
__device__ __forceinline__ void split2(float a, float b, uint32_t& hi, uint32_t& lo) {
    __nv_bfloat16 ah = __float2bfloat16(a), bh = __float2bfloat16(b);
    __nv_bfloat16 al = __float2bfloat16(a - __bfloat162float(ah));
    __nv_bfloat16 bl = __float2bfloat16(b - __bfloat162float(bh));
    hi = (uint32_t)__bfloat16_as_ushort(ah) | ((uint32_t)__bfloat16_as_ushort(bh) << 16);
    lo = (uint32_t)__bfloat16_as_ushort(al) | ((uint32_t)__bfloat16_as_ushort(bl) << 16);
}

// ---------------- kernel 1: split W into bf16 hi/lo ----------------
__global__ void wsplit_kernel(const float* __restrict__ Wb,
                              const float* __restrict__ Ws) {
    int t = blockIdx.x * 256 + threadIdx.x;       // [0, 256*2304)
    int o = t / K_TOT;
    int k = t - o * K_TOT;
    float v = (k < IN_F) ? Wb[(size_t)o * IN_F + k]
                         : Ws[(size_t)o * K_SPL + (k - IN_F)];
    __nv_bfloat16 h = __float2bfloat16(v);
    __nv_bfloat16 l = __float2bfloat16(v - __bfloat162float(h));
    g_w_hi[t] = h;
    g_w_lo[t] = l;
}

// ---------------- kernel 2: fused mma.sync KAN GEMM ----------------
// C[N_ROWS, OUT_F] = F @ W^T, F generated on the fly as bf16 hi/lo splits.
// 8 warps: 4(M) x 2(N) -> 32x64 per warp; m16n8k16 HMMA; fp32 accumulators.
// Double-buffered SMEM chunks of K=64; one __syncthreads per chunk.
__global__ __launch_bounds__(256, 1) void kan_mma_kernel(
    const float* __restrict__ x, float* __restrict__ out)
{
    extern __shared__ __nv_bfloat16 sm[];
    const uint32_t sb = smem_u32(sm);
    const int tid  = threadIdx.x;
    const int wid  = tid >> 5;
    const int lane = tid & 31;
    const int n0 = blockIdx.y * BM;
    const int o0 = blockIdx.x * BN;
    const int mw = (wid >> 1) * 32;   // warp M base within tile
    const int nw = (wid & 1) * 64;    // warp N base within tile

    float acc[2][8][4];               // [mi 16-row][n8 8-col][frag]
    #pragma unroll
    for (int a = 0; a < 2; ++a)
        #pragma unroll
        for (int b = 0; b < 8; ++b)
            #pragma unroll
            for (int q = 0; q < 4; ++q) acc[a][b][q] = 0.0f;

    // ---- stage chunk c into buffer buf (0/1): Ah|Al|Bh|Bl, padded rows ----
    auto stage = [&](int c, int buf) {
        __nv_bfloat16* stg = sm + buf * STAGE_E;
        const int k0 = c * KC;
        // B: [128 o-rows x 64 k] hi/lo from pre-split weights
        #pragma unroll
        for (int p = 0; p < 4; ++p) {
            int u   = tid + p * 256;          // [0,1024)
            int row = u >> 3;
            int kq  = (u & 7) * 8;
            size_t gi = (size_t)(o0 + row) * K_TOT + k0 + kq;
            uint4 vh = *reinterpret_cast<const uint4*>(&g_w_hi[gi]);
            uint4 vl = *reinterpret_cast<const uint4*>(&g_w_lo[gi]);
            uint32_t e = row * LDA + kq;      // elem offset
            uint2* dh = reinterpret_cast<uint2*>(stg + 2 * TILE_E + e);
            uint2* dl = reinterpret_cast<uint2*>(stg + 3 * TILE_E + e);
            dh[0] = make_uint2(vh.x, vh.y); dh[1] = make_uint2(vh.z, vh.w);
            dl[0] = make_uint2(vl.x, vl.y); dl[1] = make_uint2(vl.z, vl.w);
        }
        // A: computed features, hi/lo
        if (k0 < IN_F) {
            #pragma unroll
            for (int p = 0; p < 16; ++p) {
                int q   = tid + p * 256;       // [0,4096) col-pairs
                int row = q >> 5;
                int col = (q & 31) * 2;
                float2 xv = *reinterpret_cast<const float2*>(
                    &x[(size_t)(n0 + row) * IN_F + k0 + col]);
                uint32_t hi, lo;
                split2(silu_f(xv.x), silu_f(xv.y), hi, lo);
                uint32_t e = row * LDA + col;
                *reinterpret_cast<uint32_t*>(stg + 0 * TILE_E + e) = hi;
                *reinterpret_cast<uint32_t*>(stg + 1 * TILE_E + e) = lo;
            }
        } else {
            const int i0 = (k0 - IN_F) >> 3;   // 8 features per chunk
            #pragma unroll
            for (int p = 0; p < 4; ++p) {
                int w   = tid + p * 256;       // [0,1024)
                int row = w >> 3;
                int f   = w & 7;
                float xv = x[(size_t)(n0 + row) * IN_F + i0 + f];
                float bb[8];
                bspline8(xv, bb);
                uint32_t hw[4], lw[4];
                #pragma unroll
                for (int q = 0; q < 4; ++q)
                    split2(bb[2 * q], bb[2 * q + 1], hw[q], lw[q]);
                uint32_t e = row * LDA + f * 8;
                uint2* dh = reinterpret_cast<uint2*>(stg + 0 * TILE_E + e);
                uint2* dl = reinterpret_cast<uint2*>(stg + 1 * TILE_E + e);
                dh[0] = make_uint2(hw[0], hw[1]); dh[1] = make_uint2(hw[2], hw[3]);
                dl[0] = make_uint2(lw[0], lw[1]); dl[1] = make_uint2(lw[2], lw[3]);
            }
        }
    };

    // ---- HMMA on a staged buffer ----
    auto mma_chunk = [&](int buf) {
        const uint32_t base = sb + buf * (STAGE_E * 2);   // bytes
        // ldmatrix address pieces
        const int ar = lane & 15;            // A row within 16
        const int ac = (lane >> 4) * 8;      // A col 0/8
        const int bn = (lane >> 4) * 8 + (lane & 7);   // B n within 16
        const int bk = ((lane >> 3) & 1) * 8;          // B k 0/8
        #pragma unroll
        for (int ki = 0; ki < 4; ++ki) {
            const int kk = ki * 16;
            uint32_t ah[2][4], al[2][4];
            #pragma unroll
            for (int mi = 0; mi < 2; ++mi) {
                uint32_t off = ((mw + mi * 16 + ar) * LDA + kk + ac) * 2;
                ldsm_x4(ah[mi], base + 0 * TILE_E * 2 + off);
                ldsm_x4(al[mi], base + 1 * TILE_E * 2 + off);
            }
            #pragma unroll
            for (int np = 0; np < 4; ++np) {
                uint32_t boff = ((nw + np * 16 + bn) * LDA + kk + bk) * 2;
                uint32_t bh[4], bl[4];
                ldsm_x4(bh, base + 2 * TILE_E * 2 + boff);
                ldsm_x4(bl, base + 3 * TILE_E * 2 + boff);
                #pragma unroll
                for (int mi = 0; mi < 2; ++mi) {
                    mma_bf16(acc[mi][np * 2 + 0], ah[mi], bh[0], bh[1]);
                    mma_bf16(acc[mi][np * 2 + 1], ah[mi], bh[2], bh[3]);
                    mma_bf16(acc[mi][np * 2 + 0], ah[mi], bl[0], bl[1]);
                    mma_bf16(acc[mi][np * 2 + 1], ah[mi], bl[2], bl[3]);
                    mma_bf16(acc[mi][np * 2 + 0], al[mi], bh[0], bh[1]);
                    mma_bf16(acc[mi][np * 2 + 1], al[mi], bh[2], bh[3]);
                }
            }
        }
    };

    stage(0, 0);
    __syncthreads();
    for (int c = 0; c < NCH; ++c) {
        const int s = c & 1;
        mma_chunk(s);                      // reads buf s
        if (c + 1 < NCH) stage(c + 1, 1 - s);   // writes buf 1-s (no hazard)
        __syncthreads();
    }

    // ---- epilogue: write 32x64 warp tile (fragment rows l/4, cols (l%4)*2) ----
    const int cr = lane >> 2;
    const int ccol = (lane & 3) * 2;
    #pragma unroll
    for (int mi = 0; mi < 2; ++mi) {
        #pragma unroll
        for (int j = 0; j < 8; ++j) {
            int r = n0 + mw + mi * 16 + cr;
            int cg = o0 + nw + j * 8 + ccol;
            *reinterpret_cast<float2*>(&out[(size_t)r * OUT_F + cg]) =
                make_float2(acc[mi][j][0], acc[mi][j][1]);
            *reinterpret_cast<float2*>(&out[(size_t)(r + 8) * OUT_F + cg]) =
                make_float2(acc[mi][j][2], acc[mi][j][3]);
        }
    }
}

// ---------------------------------------------------------------------------
extern "C" void kernel_launch(void* const* d_in, const int* in_sizes, int n_in,
                              void* d_out, int out_size) {
    const float* x  = (const float*)d_in[0];   // [8, 4096, 256]
    const float* wb = (const float*)d_in[1];   // [256, 256]
    const float* ws = (const float*)d_in[2];   // [256, 256, 8]
    float* out = (float*)d_out;                // [8, 4096, 256]

    cudaFuncSetAttribute(kan_mma_kernel,
                         cudaFuncAttributeMaxDynamicSharedMemorySize, SM_BYTES);

    wsplit_kernel<<<(OUT_F * K_TOT) / 256, 256>>>(wb, ws);

    dim3 grid(OUT_F / BN, N_ROWS / BM);        // (2, 256)
    kan_mma_kernel<<<grid, 256, SM_BYTES>>>(x, out);
}